// round 16
// baseline (speedup 1.0000x reference)
#include <cuda_runtime.h>
#include <cuda_fp16.h>
#include <cstdint>

// ---------------- problem constants ----------------
#define RR 200
#define NN 16
#define FF 512
#define DD 128
#define NUML 3
#define TOKENS 4096
#define MTOT (RR*NN)    // 3200
#define KSP (2*FF)      // 1024 logical split-K: A'=[Ah|Al] fp16; B has 512 cols (reused)
#define NSTAGE 8        // fused: 8 stages x 128 cols

// ---------------- device scratch ----------------
__device__ float g_out_r[RR*DD];
__device__ float g_preX[4][MTOT*DD];         // layer-2 X = e2 @ W_lo2 partials (per nt)
__device__ __half g_msgA[MTOT*KSP];          // A' ping
__device__ __half g_msgB[MTOT*KSP];          // A' pong
__device__ __half g_Wll[NUML*FF*FF];         // Bh, [l][n][k] (deduplicated)
__device__ __half g_Wlo[NUML*DD*FF];

#define SWZ(x) ((x) ^ (((x) >> 3) & 0x70))

__device__ __forceinline__ uint32_t smem_u32(const void* p) {
    uint32_t a;
    asm("{ .reg .u64 t; cvta.to.shared.u64 t, %1; cvt.u32.u64 %0, t; }" : "=r"(a) : "l"(p));
    return a;
}
__device__ __forceinline__ void cp16(uint32_t dst, const void* src) {
    asm volatile("cp.async.cg.shared.global [%0], [%1], 16;" :: "r"(dst), "l"(src));
}
#define CP_COMMIT() asm volatile("cp.async.commit_group;" ::: "memory")
#define CP_WAIT(n)  asm volatile("cp.async.wait_group %0;" :: "n"(n) : "memory")

#define LDSM4(r, addr) \
    asm volatile("ldmatrix.sync.aligned.m8n8.x4.shared.b16 {%0,%1,%2,%3}, [%4];" \
        : "=r"((r)[0]), "=r"((r)[1]), "=r"((r)[2]), "=r"((r)[3]) : "r"(addr))

#define MMA16816(d, a, b0v, b1v) \
    asm volatile("mma.sync.aligned.m16n8k16.row.col.f32.f16.f16.f32 " \
        "{%0,%1,%2,%3}, {%4,%5,%6,%7}, {%8,%9}, {%0,%1,%2,%3};" \
        : "+f"((d)[0]), "+f"((d)[1]), "+f"((d)[2]), "+f"((d)[3]) \
        : "r"((a)[0]), "r"((a)[1]), "r"((a)[2]), "r"((a)[3]), "r"(b0v), "r"(b1v))

__device__ __forceinline__ void split_pack(float sx, float sy, uint32_t& hv, uint32_t& lv) {
    __half hx = __float2half_rn(sx), hy = __float2half_rn(sy);
    __half lx = __float2half_rn(sx - __half2float(hx));
    __half ly = __float2half_rn(sy - __half2float(hy));
    __half2 hp = __halves2half2(hx, hy), lp = __halves2half2(lx, ly);
    hv = *(uint32_t*)&hp; lv = *(uint32_t*)&lp;
}

// ---------------- merged prep (weights transpose fp16) + layer-0 msg ----------------
__global__ __launch_bounds__(256) void prep_msg0_kernel(
    const float* __restrict__ W_ll, const float* __restrict__ W_lo,
    const float* __restrict__ init_embed, const float* __restrict__ adj)
{
    __shared__ float sh[2368];
    const int b = blockIdx.x, t = threadIdx.x;
    if (b < 1536) {
        float (*tile)[33] = (float(*)[33])sh;
        const int bx = b & 15, by = (b >> 4) & 15, z = b >> 8;
        const int is_lo = (z >= 3);
        if (is_lo && by >= 4) return;
        const int l = is_lo ? z - 3 : z;
        const int k0 = bx*32, n0 = by*32;
        const int nd = is_lo ? DD : FF;
        const float* W = is_lo ? W_lo : W_ll;
        __half* G = is_lo ? g_Wlo : g_Wll;
        const int nrow = is_lo ? DD : FF;
        #pragma unroll
        for (int u = 0; u < 4; u++) {
            const int idx = t + 256*u;
            const int kk = idx >> 5, nn = idx & 31;
            tile[kk][nn] = W[(size_t)(l*FF + k0 + kk)*nd + n0 + nn];
        }
        __syncthreads();
        #pragma unroll
        for (int u = 0; u < 4; u++) {
            const int idx = t + 256*u;
            const int nn = idx >> 5, kk = idx & 31;
            G[(size_t)(l*nrow + n0 + nn)*FF + k0 + kk] = __float2half_rn(tile[kk][nn]);
        }
    } else {
        float* e_s = sh;            // 16*132
        float* a_s = sh + 2112;     // 256
        const int idx2 = b - 1536;
        const int rule = idx2 >> 2, c0 = (idx2 & 3)*128;
        if ((idx2 & 3) == 0 && rule < 100) g_out_r[rule*256 + t] = 0.f;
        a_s[t] = adj[rule*256 + t];
        #pragma unroll
        for (int u = 0; u < 2; u++) {
            const int idx = t + 256*u;
            const int row = idx >> 5, q = idx & 31;
            *(float4*)&e_s[row*132 + q*4] =
                *(const float4*)(init_embed + (size_t)(rule*NN + row)*FF + c0 + q*4);
        }
        __syncthreads();
        const int col2 = t & 63, grp = t >> 6;
        float2 ev[16];
        #pragma unroll
        for (int j = 0; j < 16; j++) ev[j] = *(float2*)&e_s[j*132 + col2*2];
        #pragma unroll
        for (int ii = 0; ii < 4; ii++) {
            const int i = grp*4 + ii;
            float sx = 0.f, sy = 0.f;
            #pragma unroll
            for (int j = 0; j < 16; j++) {
                const float av = a_s[i*16 + j];
                sx += av*ev[j].x; sy += av*ev[j].y;
            }
            uint32_t hv, lv; split_pack(sx, sy, hv, lv);
            __half* p = g_msgA + (size_t)(rule*NN + i)*KSP + c0 + col2*2;
            *(uint32_t*)(p)      = hv;
            *(uint32_t*)(p + FF) = lv;
        }
    }
}

// ---------------- fused HMMA GEMM (layers 0,1): grid (25,5), 512 threads ----------------
// mode 0, last==0: ll tile -> relu + next-layer msg into msg_w
// mode 0, last==1: ll tile -> relu -> X = e2split @ W_lo2-slice partials into g_preX[nt]
// mode 1 (by==4): lo pool += g_out_r (layers 0,1)
#define STG_BYTES 65536
#define SM_AS (3*STG_BYTES)
#define SM_BYTES (SM_AS + 8192)      // 204800

__global__ __launch_bounds__(512, 1) void fused_gemm_kernel(
    int l, int abuf, int last,
    const float* __restrict__ b_ll, const float* __restrict__ b_lo,
    const float* __restrict__ mask, const float* __restrict__ adjp)
{
    extern __shared__ char smem[];
    const uint32_t sb = smem_u32(smem);
    const int t = threadIdx.x, lid = t & 31, wid = t >> 5;
    const int warp_m = wid & 3, warp_n = wid >> 2;   // 4x4 -> 32x32 tiles
    const int mt = blockIdx.x;
    const int mode = (blockIdx.y == 4) ? 1 : 0;
    const int nt = mode ? 0 : blockIdx.y;

    const __half* msg_r = abuf ? g_msgB : g_msgA;
    __half*       msg_w = abuf ? g_msgA : g_msgB;

    const __half* Arow = msg_r + (size_t)mt * 128 * KSP;
    const __half* Brow = (mode ? (g_Wlo + (size_t)l*DD*FF)
                               : (g_Wll + (size_t)l*FF*FF + (size_t)nt*128*FF));

    float* a_s2 = (float*)(smem + SM_AS);
    if (mode == 0 && !last) {
        #pragma unroll
        for (int u = 0; u < 4; u++)
            a_s2[t + 512*u] = adjp[(size_t)mt*2048 + t + 512*u];
    }

    const int r_ld[2] = { t >> 3, (t + 512) >> 3 };
    const int g_ld = t & 7;
    const uint32_t so_ld[2] = {
        SWZ((uint32_t)(r_ld[0]*128 + g_ld*16)), SWZ((uint32_t)(r_ld[1]*128 + g_ld*16)) };

    const int lid15 = lid & 15, lidh = lid >> 4;
    uint32_t a_off[2][4], b_off[2][4];
    #pragma unroll
    for (int ks = 0; ks < 4; ks++) {
        const uint32_t grp = ks*2 + lidh;
        #pragma unroll
        for (int m2 = 0; m2 < 2; m2++)
            a_off[m2][ks] = SWZ((uint32_t)((warp_m*32 + m2*16 + lid15)*128 + grp*16));
        #pragma unroll
        for (int n2 = 0; n2 < 2; n2++)
            b_off[n2][ks] = SWZ((uint32_t)((warp_n*32 + n2*16 + lid15)*128 + grp*16));
    }

    float acc[2][4][4];
    #pragma unroll
    for (int i = 0; i < 2; i++)
        #pragma unroll
        for (int j = 0; j < 4; j++)
            #pragma unroll
            for (int k = 0; k < 4; k++) acc[i][j][k] = 0.f;

    auto load_stage = [&](int st, int buf) {
        const uint32_t ab = sb + buf*STG_BYTES;
        #pragma unroll
        for (int h = 0; h < 2; h++) {
            const int ck = st*2 + h;          // A subchunk 0..15
            const int cb = ck & 7;            // B subchunk wraps mod 512 cols
            #pragma unroll
            for (int u = 0; u < 2; u++) {
                cp16(ab + h*16384 + so_ld[u],
                     Arow + (size_t)r_ld[u]*KSP + ck*64 + g_ld*8);
                cp16(ab + 32768 + h*16384 + so_ld[u],
                     Brow + (size_t)r_ld[u]*FF + cb*64 + g_ld*8);
            }
        }
    };

    load_stage(0, 0); CP_COMMIT();
    load_stage(1, 1); CP_COMMIT();

    for (int st = 0; st < NSTAGE; st++) {
        if (st + 2 < NSTAGE) CP_WAIT(1); else CP_WAIT(0);
        __syncthreads();
        if (st + 2 < NSTAGE) { load_stage(st + 2, (st + 2) % 3); CP_COMMIT(); }

        const uint32_t ab = sb + (st % 3)*STG_BYTES;
        #pragma unroll
        for (int h = 0; h < 2; h++) {
            const uint32_t aB = ab + h*16384, bB = ab + 32768 + h*16384;
            #pragma unroll
            for (int ks = 0; ks < 4; ks++) {
                uint32_t af0[4], af1[4], bf0[4], bf1[4];
                LDSM4(af0, aB + a_off[0][ks]);
                LDSM4(af1, aB + a_off[1][ks]);
                LDSM4(bf0, bB + b_off[0][ks]);
                LDSM4(bf1, bB + b_off[1][ks]);
                MMA16816(acc[0][0], af0, bf0[0], bf0[2]);
                MMA16816(acc[0][1], af0, bf0[1], bf0[3]);
                MMA16816(acc[0][2], af0, bf1[0], bf1[2]);
                MMA16816(acc[0][3], af0, bf1[1], bf1[3]);
                MMA16816(acc[1][0], af1, bf0[0], bf0[2]);
                MMA16816(acc[1][1], af1, bf0[1], bf0[3]);
                MMA16816(acc[1][2], af1, bf1[0], bf1[2]);
                MMA16816(acc[1][3], af1, bf1[1], bf1[3]);
            }
        }
    }
    __syncthreads();   // all warps done reading stage smem before epilogue reuse

    // ---------------- epilogue ----------------
    if (mode == 0 && !last) {
        float* e_s = (float*)smem;   // [128][132]
        const float* bias = b_ll + l*FF + nt*128;
        #pragma unroll
        for (int m2 = 0; m2 < 2; m2++) {
            const int row = warp_m*32 + m2*16 + (lid >> 2);
            #pragma unroll
            for (int j = 0; j < 4; j++) {
                const int colL = warp_n*32 + j*8 + (lid & 3)*2;
                const float bx = bias[colL], by = bias[colL+1];
                float2 v0, v1;
                v0.x = fmaxf(acc[m2][j][0] + bx, 0.f);
                v0.y = fmaxf(acc[m2][j][1] + by, 0.f);
                v1.x = fmaxf(acc[m2][j][2] + bx, 0.f);
                v1.y = fmaxf(acc[m2][j][3] + by, 0.f);
                *(float2*)&e_s[row*132 + colL]     = v0;
                *(float2*)&e_s[(row+8)*132 + colL] = v1;
            }
        }
        __syncthreads();

        const int col2 = t & 63, rl = t >> 6;
        float2 ev[16];
        #pragma unroll
        for (int j = 0; j < 16; j++)
            ev[j] = *(float2*)&e_s[(rl*16 + j)*132 + col2*2];
        const float* arow = a_s2 + rl*256;
        __half* wbase = msg_w + (size_t)(mt*128 + rl*16)*KSP + nt*128 + col2*2;
        #pragma unroll
        for (int i = 0; i < 16; i++) {
            float sx = 0.f, sy = 0.f;
            #pragma unroll
            for (int j = 0; j < 16; j++) {
                const float av = arow[i*16 + j];
                sx += av*ev[j].x; sy += av*ev[j].y;
            }
            uint32_t hv, lv; split_pack(sx, sy, hv, lv);
            __half* p = wbase + (size_t)i*KSP;
            *(uint32_t*)(p)      = hv;
            *(uint32_t*)(p + FF) = lv;
        }
    } else if (mode == 0) {
        // last: X-partial epilogue. Load W_lo2 k-slice (async), build E'=[Eh|El] in smem.
        #pragma unroll
        for (int h = 0; h < 2; h++)
            #pragma unroll
            for (int u = 0; u < 2; u++)
                cp16(sb + h*16384 + so_ld[u],
                     g_Wlo + (size_t)(2*DD + r_ld[u])*FF + nt*128 + h*64 + g_ld*8);
        CP_COMMIT();

        const float* bias = b_ll + l*FF + nt*128;
        #pragma unroll
        for (int m2 = 0; m2 < 2; m2++) {
            const int row0 = warp_m*32 + m2*16 + (lid >> 2);
            #pragma unroll
            for (int j = 0; j < 4; j++) {
                const int colL = warp_n*32 + j*8 + (lid & 3)*2;
                const float bx = bias[colL], by = bias[colL+1];
                const float e0x = fmaxf(acc[m2][j][0] + bx, 0.f);
                const float e0y = fmaxf(acc[m2][j][1] + by, 0.f);
                const float e1x = fmaxf(acc[m2][j][2] + bx, 0.f);
                const float e1y = fmaxf(acc[m2][j][3] + by, 0.f);
                uint32_t h0, l0, h1, l1;
                split_pack(e0x, e0y, h0, l0);
                split_pack(e1x, e1y, h1, l1);
                const uint32_t sub = (uint32_t)(colL >> 6) * 16384u;
                const uint32_t off0 = sub + SWZ((uint32_t)(row0*128 + (colL & 63)*2));
                const uint32_t off1 = sub + SWZ((uint32_t)((row0+8)*128 + (colL & 63)*2));
                *(uint32_t*)(smem + 32768 + off0) = h0;   // Eh
                *(uint32_t*)(smem + 65536 + off0) = l0;   // El
                *(uint32_t*)(smem + 32768 + off1) = h1;
                *(uint32_t*)(smem + 65536 + off1) = l1;
            }
        }
        CP_WAIT(0);
        __syncthreads();

        float xacc[2][4][4];
        #pragma unroll
        for (int i = 0; i < 2; i++)
            #pragma unroll
            for (int j = 0; j < 4; j++)
                #pragma unroll
                for (int k = 0; k < 4; k++) xacc[i][j][k] = 0.f;

        #pragma unroll
        for (int src = 0; src < 2; src++) {       // Eh pass, then El pass
            #pragma unroll
            for (int h = 0; h < 2; h++) {
                const uint32_t aB = sb + 32768 + src*32768 + h*16384;
                const uint32_t bB = sb + h*16384;  // W_lo2 slice
                #pragma unroll
                for (int ks = 0; ks < 4; ks++) {
                    uint32_t af0[4], af1[4], bf0[4], bf1[4];
                    LDSM4(af0, aB + a_off[0][ks]);
                    LDSM4(af1, aB + a_off[1][ks]);
                    LDSM4(bf0, bB + b_off[0][ks]);
                    LDSM4(bf1, bB + b_off[1][ks]);
                    MMA16816(xacc[0][0], af0, bf0[0], bf0[2]);
                    MMA16816(xacc[0][1], af0, bf0[1], bf0[3]);
                    MMA16816(xacc[0][2], af0, bf1[0], bf1[2]);
                    MMA16816(xacc[0][3], af0, bf1[1], bf1[3]);
                    MMA16816(xacc[1][0], af1, bf0[0], bf0[2]);
                    MMA16816(xacc[1][1], af1, bf0[1], bf0[3]);
                    MMA16816(xacc[1][2], af1, bf1[0], bf1[2]);
                    MMA16816(xacc[1][3], af1, bf1[1], bf1[3]);
                }
            }
        }

        float* P = g_preX[nt];
        #pragma unroll
        for (int m2 = 0; m2 < 2; m2++) {
            const int r0 = mt*128 + warp_m*32 + m2*16 + (lid >> 2);
            #pragma unroll
            for (int j = 0; j < 4; j++) {
                const int n = warp_n*32 + j*8 + (lid & 3)*2;
                *(float2*)&P[(size_t)r0*DD + n]     = make_float2(xacc[m2][j][0], xacc[m2][j][1]);
                *(float2*)&P[(size_t)(r0+8)*DD + n] = make_float2(xacc[m2][j][2], xacc[m2][j][3]);
            }
        }
    } else {
        const float* bias = b_lo + l*DD;
        #pragma unroll
        for (int m2 = 0; m2 < 2; m2++) {
            const int rbase = mt*128 + warp_m*32 + m2*16;
            const int rule = rbase >> 4;
            const float m0 = mask[rbase + (lid >> 2)];
            const float m1 = mask[rbase + (lid >> 2) + 8];
            #pragma unroll
            for (int j = 0; j < 4; j++) {
                const int n = warp_n*32 + j*8 + (lid & 3)*2;
                const float bx = bias[n], by = bias[n+1];
                float sx = tanhf(acc[m2][j][0] + bx)*m0 + tanhf(acc[m2][j][2] + bx)*m1;
                float sy = tanhf(acc[m2][j][1] + by)*m0 + tanhf(acc[m2][j][3] + by)*m1;
                sx += __shfl_xor_sync(0xffffffffu, sx, 4);
                sx += __shfl_xor_sync(0xffffffffu, sx, 8);
                sx += __shfl_xor_sync(0xffffffffu, sx, 16);
                sy += __shfl_xor_sync(0xffffffffu, sy, 4);
                sy += __shfl_xor_sync(0xffffffffu, sy, 8);
                sy += __shfl_xor_sync(0xffffffffu, sy, 16);
                if ((lid >> 2) == 0) {
                    g_out_r[rule*DD + n]     += sx;
                    g_out_r[rule*DD + n + 1] += sy;
                }
            }
        }
    }
}

// ---------------- finish: layer-2 pool, smem-staged, one CTA per rule ----------------
// Xs[j][col] = sum of 4 nt partials (coalesced float4 loads), then
// out_r[rule] += sum_i tanh( (A @ Xs)[i] + b )*mask[i]
__global__ __launch_bounds__(256) void finish_kernel(
    const float* __restrict__ b_lo, const float* __restrict__ mask,
    const float* __restrict__ adj)
{
    __shared__ float Xs[NN*DD];      // 16 x 128
    __shared__ float a_s[256];
    __shared__ float part[DD];
    const int t = threadIdx.x;
    const int rule = blockIdx.x;
    a_s[t] = adj[rule*256 + t];
    // stage X sum: 2048 floats = 512 float4, 2 per thread, coalesced across 4 buffers
    #pragma unroll
    for (int u = 0; u < 2; u++) {
        const int i4 = t + 256*u;
        const size_t base = (size_t)rule*NN*(DD/4) + i4;
        const float4 x0 = ((const float4*)g_preX[0])[base];
        const float4 x1 = ((const float4*)g_preX[1])[base];
        const float4 x2 = ((const float4*)g_preX[2])[base];
        const float4 x3 = ((const float4*)g_preX[3])[base];
        float4 s4;
        s4.x = x0.x + x1.x + x2.x + x3.x;
        s4.y = x0.y + x1.y + x2.y + x3.y;
        s4.z = x0.z + x1.z + x2.z + x3.z;
        s4.w = x0.w + x1.w + x2.w + x3.w;
        ((float4*)Xs)[i4] = s4;
    }
    __syncthreads();
    const int half = t >> 7, col = t & 127;
    const float bias = b_lo[2*DD + col];
    float s = 0.f;
    #pragma unroll
    for (int i = 0; i < 8; i++) {
        const int row = half*8 + i;
        float y = 0.f;
        #pragma unroll
        for (int j = 0; j < 16; j++) y += a_s[row*16 + j] * Xs[j*DD + col];
        s += tanhf(y + bias) * mask[rule*NN + row];
    }
    if (half == 1) part[col] = s;
    __syncthreads();
    if (half == 0) g_out_r[rule*DD + col] += s + part[col];
}

// ---------------- gather: warp = one token ----------------
__global__ __launch_bounds__(256) void gather_kernel(const int* __restrict__ idx,
                                                     float4* __restrict__ out)
{
    const int gtid = blockIdx.x * blockDim.x + threadIdx.x;
    const int tok = gtid >> 5, lane = gtid & 31;
    if (tok >= TOKENS) return;
    int r = 0;
    if (lane == 0) r = idx[tok];
    r = __shfl_sync(0xffffffffu, r, 0);
    float4 v = make_float4(0.f, 0.f, 0.f, 0.f);
    if (r < RR) v = ((const float4*)g_out_r)[r*(DD/4) + lane];
    out[tok*(DD/4) + lane] = v;
}

// ---------------- launch (single stream, sequential) ----------------
extern "C" void kernel_launch(void* const* d_in, const int* in_sizes, int n_in,
                              void* d_out, int out_size)
{
    const int*   idx        = (const int*)  d_in[0];
    const float* adj        = (const float*)d_in[1];
    const float* init_embed = (const float*)d_in[2];
    const float* node_mask  = (const float*)d_in[3];
    const float* W_ll       = (const float*)d_in[4];
    const float* b_ll       = (const float*)d_in[5];
    const float* W_lo       = (const float*)d_in[6];
    const float* b_lo       = (const float*)d_in[7];
    float* out = (float*)d_out;

    cudaFuncSetAttribute(fused_gemm_kernel,
                         cudaFuncAttributeMaxDynamicSharedMemorySize, SM_BYTES);

    prep_msg0_kernel<<<2336, 256>>>(W_ll, W_lo, init_embed, adj);
    fused_gemm_kernel<<<dim3(25,5), 512, SM_BYTES>>>(0, 0, 0, b_ll, b_lo, node_mask, adj);
    fused_gemm_kernel<<<dim3(25,5), 512, SM_BYTES>>>(1, 1, 1, b_ll, b_lo, node_mask, adj);
    finish_kernel<<<RR, 256>>>(b_lo, node_mask, adj);
    gather_kernel<<<(TOKENS*32 + 255)/256, 256>>>(idx, (float4*)out);
}